// round 3
// baseline (speedup 1.0000x reference)
#include <cuda_runtime.h>
#include <stdint.h>
#include <math.h>

#define THREADS 512
#define TILE    128
#define TPG     2      // tiles per block
#define GPB     8      // blocks per batch: 8*2*128 = 2048 rows covered
#define LDIM    2048
#define BDIM    128

typedef unsigned long long u64;

__device__ __forceinline__ u64 ffma2(u64 a, u64 b, u64 c) {
    u64 d;
    asm("fma.rn.f32x2 %0, %1, %2, %3;" : "=l"(d) : "l"(a), "l"(b), "l"(c));
    return d;
}
__device__ __forceinline__ u64 rep2(float x) {
    u64 r;
    asm("mov.b64 %0, {%1, %1};" : "=l"(r) : "f"(x));
    return r;
}
__device__ __forceinline__ float2 unpack2(u64 v) {
    float2 f;
    asm("mov.b64 {%0, %1}, %2;" : "=f"(f.x), "=f"(f.y) : "l"(v));
    return f;
}

template<int NEMB>
struct Cfg {
    static constexpr int GEO = (NEMB == 4) ? 2 : 1;
    static constexpr int IN  = GEO + NEMB * 16;
    static constexpr int XST = (IN + 3) & ~3;    // padded x row stride (floats)
    static constexpr int NROWS = LDIM - NEMB + 1;
    static constexpr int SMEM_FLOATS =
        XST * 128         // W1 (zero-padded rows)
        + 128 * 128       // W2
        + 128 + 128 + 128 // b1, b2, W3
        + 320             // emb (20x16)
        + TILE * XST      // x tile (padded)
        + TILE * 128      // h1 tile
        + 132             // seq slice (ints)
        + 4;              // block sum + pad
    static constexpr int SMEM_BYTES = SMEM_FLOATS * 4;
};

__global__ void zero_kernel(float* out, int n) {
    int i = blockIdx.x * blockDim.x + threadIdx.x;
    if (i < n) out[i] = 0.f;
}

template<int NEMB>
__global__ __launch_bounds__(THREADS, 1)
void mlp_energy_kernel(const float* __restrict__ R,
                       const int*   __restrict__ seq,
                       const float* __restrict__ emb,
                       const float* __restrict__ gW1, const float* __restrict__ gb1,
                       const float* __restrict__ gW2, const float* __restrict__ gb2,
                       const float* __restrict__ gW3, const float* __restrict__ gb3,
                       float* __restrict__ out)
{
    constexpr int GEO   = Cfg<NEMB>::GEO;
    constexpr int IN    = Cfg<NEMB>::IN;
    constexpr int XST   = Cfg<NEMB>::XST;
    constexpr int NROWS = Cfg<NEMB>::NROWS;

    extern __shared__ float smem[];
    float* W1s  = smem;                       // XST*128 (zero padded)
    float* W2s  = W1s + XST * 128;            // 128*128
    float* b1s  = W2s + 128 * 128;            // 128
    float* b2s  = b1s + 128;                  // 128
    float* W3s  = b2s + 128;                  // 128
    float* embs = W3s + 128;                  // 320
    float* xs   = embs + 320;                 // TILE*XST
    float* h1s  = xs + TILE * XST;            // TILE*128
    int*   seqs = (int*)(h1s + TILE * 128);   // 132 ints
    float* bsum = (float*)(seqs + 132);       // 1

    const int tid = threadIdx.x;

    // ---- stage weights / emb into shared ----
    for (int i = tid; i < XST * 128; i += THREADS)
        W1s[i] = (i < IN * 128) ? gW1[i] : 0.f;
    for (int i = tid; i < 128 * 128; i += THREADS) W2s[i] = gW2[i];
    if (tid < 128) { b1s[tid] = gb1[tid]; b2s[tid] = gb2[tid]; W3s[tid] = gW3[tid]; }
    for (int i = tid; i < 320; i += THREADS) embs[i] = emb[i];
    if (tid == 0) *bsum = 0.f;

    // zero x-tile padding columns once
    constexpr int PAD = XST - IN;
    for (int i = tid; i < TILE * PAD; i += THREADS) {
        int r = i / PAD, c = i - r * PAD;
        xs[r * XST + IN + c] = 0.f;
    }

    const int batch = blockIdx.x / GPB;
    const int group = blockIdx.x % GPB;
    const int wid  = tid >> 5;
    const int lane = tid & 31;
    const int half = lane >> 4;          // 0/1
    const int j0   = (lane & 15) * 8;    // 8 hidden cols per thread
    const int r0   = wid * 8 + half * 4; // 4 rows per thread
    const float b3r = gb3[0];

    const float* Rb   = R   + (size_t)batch * LDIM * 3;
    const int*   seqb = seq + (size_t)batch * LDIM;

    for (int tt = 0; tt < TPG; ++tt) {
        const int i0 = (group * TPG + tt) * TILE;

        __syncthreads();  // prev tile consumed / staging done

        // ---- seq slice ----
        if (tid < TILE + NEMB - 1) {
            int idx = i0 + tid;
            seqs[tid] = (idx < LDIM) ? seqb[idx] : 0;
        }
        __syncthreads();

        // ---- geometry features (threads 0..127, one row each) ----
        if (tid < TILE) {
            const int r = tid;
            const int i = i0 + r;
            float* xrow = xs + r * XST;
            if (i < NROWS) {
                float p0x = Rb[i*3+0],     p0y = Rb[i*3+1],     p0z = Rb[i*3+2];
                float p1x = Rb[(i+1)*3+0], p1y = Rb[(i+1)*3+1], p1z = Rb[(i+1)*3+2];
                float d0x = p1x - p0x, d0y = p1y - p0y, d0z = p1z - p0z;
                if (NEMB == 2) {
                    xrow[0] = sqrtf(d0x*d0x + d0y*d0y + d0z*d0z);
                } else if (NEMB == 3) {
                    float p2x = Rb[(i+2)*3+0], p2y = Rb[(i+2)*3+1], p2z = Rb[(i+2)*3+2];
                    float d1x = p2x - p1x, d1y = p2y - p1y, d1z = p2z - p1z;
                    float dot01 = d0x*d1x + d0y*d1y + d0z*d1z;
                    float n0 = d0x*d0x + d0y*d0y + d0z*d0z;
                    float n1 = d1x*d1x + d1y*d1y + d1z*d1z;
                    float c  = -dot01 / (sqrtf(n0) * sqrtf(n1));
                    xrow[0] = fminf(1.f, fmaxf(-1.f, c));
                } else {
                    float p2x = Rb[(i+2)*3+0], p2y = Rb[(i+2)*3+1], p2z = Rb[(i+2)*3+2];
                    float p3x = Rb[(i+3)*3+0], p3y = Rb[(i+3)*3+1], p3z = Rb[(i+3)*3+2];
                    float d1x = p2x - p1x, d1y = p2y - p1y, d1z = p2z - p1z;
                    float d2x = p3x - p2x, d2y = p3y - p2y, d2z = p3z - p2z;
                    float n1x = d0y*d1z - d0z*d1y;
                    float n1y = d0z*d1x - d0x*d1z;
                    float n1z = d0x*d1y - d0y*d1x;
                    float n2x = d1y*d2z - d1z*d2y;
                    float n2y = d1z*d2x - d1x*d2z;
                    float n2z = d1x*d2y - d1y*d2x;
                    float inv = rsqrtf(d1x*d1x + d1y*d1y + d1z*d1z);
                    float ux = d1x*inv, uy = d1y*inv, uz = d1z*inv;
                    float m1x = n1y*uz - n1z*uy;
                    float m1y = n1z*ux - n1x*uz;
                    float m1z = n1x*uy - n1y*ux;
                    float yv = m1x*n2x + m1y*n2y + m1z*n2z;
                    float xv = n1x*n2x + n1y*n2y + n1z*n2z;
                    float rinv = rsqrtf(xv*xv + yv*yv);
                    xrow[0] = yv * rinv;   // sin(phi)
                    xrow[1] = xv * rinv;   // cos(phi)
                }
            } else {
                xrow[0] = 0.f;
                if (GEO == 2) xrow[1] = 0.f;
            }
        }

        // ---- embedding features ----
        constexpr int EW = NEMB * 16;
        for (int e = tid; e < TILE * EW; e += THREADS) {
            int r   = e / EW;
            int rem = e - r * EW;
            float v = 0.f;
            if (i0 + r < NROWS) {
                int aa = seqs[r + (rem >> 4)];
                v = embs[aa * 16 + (rem & 15)];
            }
            xs[r * XST + GEO + rem] = v;
        }
        __syncthreads();

        // ============ layer 1: h1 = relu(x @ W1 + b1) ============
        u64 acc[4][4];   // [row][colpair]  colpair c -> cols j0+2c, j0+2c+1
        #pragma unroll
        for (int i = 0; i < 4; ++i)
            #pragma unroll
            for (int c = 0; c < 4; ++c) acc[i][c] = 0ULL;

        #pragma unroll 2
        for (int k = 0; k < XST; k += 4) {
            float4 xv4[4];
            #pragma unroll
            for (int i = 0; i < 4; ++i)
                xv4[i] = *(const float4*)(xs + (r0 + i) * XST + k);
            const float* xvf = (const float*)xv4;
            #pragma unroll
            for (int kk = 0; kk < 4; ++kk) {
                ulonglong2 wA = *(const ulonglong2*)(W1s + (k + kk) * 128 + j0);
                ulonglong2 wB = *(const ulonglong2*)(W1s + (k + kk) * 128 + j0 + 4);
                #pragma unroll
                for (int i = 0; i < 4; ++i) {
                    u64 xr = rep2(xvf[i * 4 + kk]);
                    acc[i][0] = ffma2(xr, wA.x, acc[i][0]);
                    acc[i][1] = ffma2(xr, wA.y, acc[i][1]);
                    acc[i][2] = ffma2(xr, wB.x, acc[i][2]);
                    acc[i][3] = ffma2(xr, wB.y, acc[i][3]);
                }
            }
        }
        {
            // bias + relu, write h1
            float bb[8];
            #pragma unroll
            for (int c = 0; c < 8; ++c) bb[c] = b1s[j0 + c];
            #pragma unroll
            for (int i = 0; i < 4; ++i) {
                float h[8];
                #pragma unroll
                for (int c = 0; c < 4; ++c) {
                    float2 v = unpack2(acc[i][c]);
                    h[2*c]   = fmaxf(v.x + bb[2*c],   0.f);
                    h[2*c+1] = fmaxf(v.y + bb[2*c+1], 0.f);
                }
                *(float4*)(h1s + (r0 + i) * 128 + j0)     = make_float4(h[0], h[1], h[2], h[3]);
                *(float4*)(h1s + (r0 + i) * 128 + j0 + 4) = make_float4(h[4], h[5], h[6], h[7]);
            }
        }
        __syncthreads();

        // ============ layer 2: relu(h1 @ W2 + b2) fused with layer-3 dot ============
        #pragma unroll
        for (int i = 0; i < 4; ++i)
            #pragma unroll
            for (int c = 0; c < 4; ++c) acc[i][c] = 0ULL;

        #pragma unroll 2
        for (int k = 0; k < 128; k += 4) {
            float4 hv4[4];
            #pragma unroll
            for (int i = 0; i < 4; ++i)
                hv4[i] = *(const float4*)(h1s + (r0 + i) * 128 + k);
            const float* hvf = (const float*)hv4;
            #pragma unroll
            for (int kk = 0; kk < 4; ++kk) {
                ulonglong2 wA = *(const ulonglong2*)(W2s + (k + kk) * 128 + j0);
                ulonglong2 wB = *(const ulonglong2*)(W2s + (k + kk) * 128 + j0 + 4);
                #pragma unroll
                for (int i = 0; i < 4; ++i) {
                    u64 hr = rep2(hvf[i * 4 + kk]);
                    acc[i][0] = ffma2(hr, wA.x, acc[i][0]);
                    acc[i][1] = ffma2(hr, wA.y, acc[i][1]);
                    acc[i][2] = ffma2(hr, wB.x, acc[i][2]);
                    acc[i][3] = ffma2(hr, wB.y, acc[i][3]);
                }
            }
        }

        // ---- epilogue: relu + dot with W3, half-warp reduce per row ----
        {
            float bb[8], w3[8];
            #pragma unroll
            for (int c = 0; c < 8; ++c) { bb[c] = b2s[j0 + c]; w3[c] = W3s[j0 + c]; }
            float p[4];
            #pragma unroll
            for (int i = 0; i < 4; ++i) {
                float s = 0.f;
                #pragma unroll
                for (int c = 0; c < 4; ++c) {
                    float2 v = unpack2(acc[i][c]);
                    s += fmaxf(v.x + bb[2*c],   0.f) * w3[2*c];
                    s += fmaxf(v.y + bb[2*c+1], 0.f) * w3[2*c+1];
                }
                p[i] = s;
            }
            // reduce across the 16 lanes covering the 128 hidden cols
            #pragma unroll
            for (int off = 8; off; off >>= 1) {
                #pragma unroll
                for (int i = 0; i < 4; ++i)
                    p[i] += __shfl_down_sync(0xffffffffu, p[i], off, 16);
            }
            if ((lane & 15) == 0) {
                float s = 0.f;
                #pragma unroll
                for (int i = 0; i < 4; ++i)
                    if (i0 + r0 + i < NROWS) s += p[i] + b3r;
                atomicAdd(bsum, s);
            }
        }
    }

    __syncthreads();
    if (tid == 0) atomicAdd(&out[batch], *bsum);
}

extern "C" void kernel_launch(void* const* d_in, const int* in_sizes, int n_in,
                              void* d_out, int out_size) {
    const float* R   = (const float*)d_in[0];
    const int*   seq = (const int*)d_in[1];
    const float* emb = (const float*)d_in[2];
    const float* fl[6]; const float* ft[6]; const float* fp[6];
    for (int i = 0; i < 6; ++i) {
        fl[i] = (const float*)d_in[3 + i];
        ft[i] = (const float*)d_in[9 + i];
        fp[i] = (const float*)d_in[15 + i];
    }
    float* out = (float*)d_out;

    cudaFuncSetAttribute(mlp_energy_kernel<2>,
        cudaFuncAttributeMaxDynamicSharedMemorySize, Cfg<2>::SMEM_BYTES);
    cudaFuncSetAttribute(mlp_energy_kernel<3>,
        cudaFuncAttributeMaxDynamicSharedMemorySize, Cfg<3>::SMEM_BYTES);
    cudaFuncSetAttribute(mlp_energy_kernel<4>,
        cudaFuncAttributeMaxDynamicSharedMemorySize, Cfg<4>::SMEM_BYTES);

    zero_kernel<<<1, 256>>>(out, out_size);

    dim3 grid(BDIM * GPB);
    mlp_energy_kernel<2><<<grid, THREADS, Cfg<2>::SMEM_BYTES>>>(
        R, seq, emb, fl[0], fl[1], fl[2], fl[3], fl[4], fl[5], out);
    mlp_energy_kernel<3><<<grid, THREADS, Cfg<3>::SMEM_BYTES>>>(
        R, seq, emb, ft[0], ft[1], ft[2], ft[3], ft[4], ft[5], out);
    mlp_energy_kernel<4><<<grid, THREADS, Cfg<4>::SMEM_BYTES>>>(
        R, seq, emb, fp[0], fp[1], fp[2], fp[3], fp[4], fp[5], out);
}

// round 4
// speedup vs baseline: 1.5287x; 1.5287x over previous
#include <cuda_runtime.h>
#include <stdint.h>
#include <math.h>

#define THREADS 512
#define TILE    128
#define TPG     2      // tiles per block
#define GPB     8      // blocks per batch: 8*2*128 = 2048 rows covered
#define LDIM    2048
#define BDIM    128

typedef unsigned long long u64;

__device__ __forceinline__ u64 ffma2(u64 a, u64 b, u64 c) {
    u64 d;
    asm("fma.rn.f32x2 %0, %1, %2, %3;" : "=l"(d) : "l"(a), "l"(b), "l"(c));
    return d;
}
__device__ __forceinline__ u64 rep2(float x) {
    u64 r;
    asm("mov.b64 %0, {%1, %1};" : "=l"(r) : "f"(x));
    return r;
}
__device__ __forceinline__ float2 unpack2(u64 v) {
    float2 f;
    asm("mov.b64 {%0, %1}, %2;" : "=f"(f.x), "=f"(f.y) : "l"(v));
    return f;
}

template<int NEMB>
struct Cfg {
    static constexpr int GEO = (NEMB == 4) ? 2 : 1;
    static constexpr int IN  = GEO + NEMB * 16;
    static constexpr int XST = (IN + 3) & ~3;    // padded x row stride (floats)
    static constexpr int NROWS = LDIM - NEMB + 1;
    static constexpr int SMEM_FLOATS =
        XST * 128         // W1 (zero-padded rows)
        + 128 * 128       // W2
        + 128 + 128 + 128 // b1, b2, W3
        + 320             // emb (20x16)
        + TILE * XST      // x tile (padded)
        + TILE * 128      // h1 tile
        + 132             // seq slice (ints)
        + 4;              // block sum + pad
    static constexpr int SMEM_BYTES = SMEM_FLOATS * 4;
};

__global__ void zero_kernel(float* out, int n) {
    int i = blockIdx.x * blockDim.x + threadIdx.x;
    if (i < n) out[i] = 0.f;
}

template<int NEMB>
__global__ __launch_bounds__(THREADS, 1)
void mlp_energy_kernel(const float* __restrict__ R,
                       const int*   __restrict__ seq,
                       const float* __restrict__ emb,
                       const float* __restrict__ gW1, const float* __restrict__ gb1,
                       const float* __restrict__ gW2, const float* __restrict__ gb2,
                       const float* __restrict__ gW3, const float* __restrict__ gb3,
                       float* __restrict__ out)
{
    constexpr int GEO   = Cfg<NEMB>::GEO;
    constexpr int IN    = Cfg<NEMB>::IN;
    constexpr int XST   = Cfg<NEMB>::XST;
    constexpr int NROWS = Cfg<NEMB>::NROWS;

    extern __shared__ float smem[];
    float* W1s  = smem;                       // XST*128 (zero padded)
    float* W2s  = W1s + XST * 128;            // 128*128
    float* b1s  = W2s + 128 * 128;            // 128
    float* b2s  = b1s + 128;                  // 128
    float* W3s  = b2s + 128;                  // 128
    float* embs = W3s + 128;                  // 320
    float* xs   = embs + 320;                 // TILE*XST
    float* h1s  = xs + TILE * XST;            // TILE*128
    int*   seqs = (int*)(h1s + TILE * 128);   // 132 ints
    float* bsum = (float*)(seqs + 132);       // 1

    const int tid = threadIdx.x;

    // ---- stage weights / emb into shared ----
    for (int i = tid; i < XST * 128; i += THREADS)
        W1s[i] = (i < IN * 128) ? gW1[i] : 0.f;
    for (int i = tid; i < 128 * 128; i += THREADS) W2s[i] = gW2[i];
    if (tid < 128) { b1s[tid] = gb1[tid]; b2s[tid] = gb2[tid]; W3s[tid] = gW3[tid]; }
    for (int i = tid; i < 320; i += THREADS) embs[i] = emb[i];
    if (tid == 0) *bsum = 0.f;

    // zero x-tile padding columns once
    constexpr int PAD = XST - IN;
    for (int i = tid; i < TILE * PAD; i += THREADS) {
        int r = i / PAD, c = i - r * PAD;
        xs[r * XST + IN + c] = 0.f;
    }

    const int batch = blockIdx.x / GPB;
    const int group = blockIdx.x % GPB;
    const int wid  = tid >> 5;
    const int lane = tid & 31;
    const int half = lane >> 4;              // 0/1
    const int c0   = (lane & 15) * 4;        // cols c0..c0+3   (covers [0,64))
    const int c1   = 64 + (lane & 15) * 4;   // cols c1..c1+3   (covers [64,128))
    const int r0   = wid * 8 + half * 4;     // 4 rows per thread
    const float b3r = gb3[0];

    const float* Rb   = R   + (size_t)batch * LDIM * 3;
    const int*   seqb = seq + (size_t)batch * LDIM;

    for (int tt = 0; tt < TPG; ++tt) {
        const int i0 = (group * TPG + tt) * TILE;

        __syncthreads();  // prev tile consumed / staging done

        // ---- seq slice ----
        if (tid < TILE + NEMB - 1) {
            int idx = i0 + tid;
            seqs[tid] = (idx < LDIM) ? seqb[idx] : 0;
        }
        __syncthreads();

        // ---- geometry features (threads 0..127, one row each) ----
        if (tid < TILE) {
            const int r = tid;
            const int i = i0 + r;
            float* xrow = xs + r * XST;
            if (i < NROWS) {
                float p0x = Rb[i*3+0],     p0y = Rb[i*3+1],     p0z = Rb[i*3+2];
                float p1x = Rb[(i+1)*3+0], p1y = Rb[(i+1)*3+1], p1z = Rb[(i+1)*3+2];
                float d0x = p1x - p0x, d0y = p1y - p0y, d0z = p1z - p0z;
                if (NEMB == 2) {
                    xrow[0] = sqrtf(d0x*d0x + d0y*d0y + d0z*d0z);
                } else if (NEMB == 3) {
                    float p2x = Rb[(i+2)*3+0], p2y = Rb[(i+2)*3+1], p2z = Rb[(i+2)*3+2];
                    float d1x = p2x - p1x, d1y = p2y - p1y, d1z = p2z - p1z;
                    float dot01 = d0x*d1x + d0y*d1y + d0z*d1z;
                    float n0 = d0x*d0x + d0y*d0y + d0z*d0z;
                    float n1 = d1x*d1x + d1y*d1y + d1z*d1z;
                    float c  = -dot01 / (sqrtf(n0) * sqrtf(n1));
                    xrow[0] = fminf(1.f, fmaxf(-1.f, c));
                } else {
                    float p2x = Rb[(i+2)*3+0], p2y = Rb[(i+2)*3+1], p2z = Rb[(i+2)*3+2];
                    float p3x = Rb[(i+3)*3+0], p3y = Rb[(i+3)*3+1], p3z = Rb[(i+3)*3+2];
                    float d1x = p2x - p1x, d1y = p2y - p1y, d1z = p2z - p1z;
                    float d2x = p3x - p2x, d2y = p3y - p2y, d2z = p3z - p2z;
                    float n1x = d0y*d1z - d0z*d1y;
                    float n1y = d0z*d1x - d0x*d1z;
                    float n1z = d0x*d1y - d0y*d1x;
                    float n2x = d1y*d2z - d1z*d2y;
                    float n2y = d1z*d2x - d1x*d2z;
                    float n2z = d1x*d2y - d1y*d2x;
                    float inv = rsqrtf(d1x*d1x + d1y*d1y + d1z*d1z);
                    float ux = d1x*inv, uy = d1y*inv, uz = d1z*inv;
                    float m1x = n1y*uz - n1z*uy;
                    float m1y = n1z*ux - n1x*uz;
                    float m1z = n1x*uy - n1y*ux;
                    float yv = m1x*n2x + m1y*n2y + m1z*n2z;
                    float xv = n1x*n2x + n1y*n2y + n1z*n2z;
                    float rinv = rsqrtf(xv*xv + yv*yv);
                    xrow[0] = yv * rinv;   // sin(phi)
                    xrow[1] = xv * rinv;   // cos(phi)
                }
            } else {
                xrow[0] = 0.f;
                if (GEO == 2) xrow[1] = 0.f;
            }
        }

        // ---- embedding features ----
        constexpr int EW = NEMB * 16;
        for (int e = tid; e < TILE * EW; e += THREADS) {
            int r   = e / EW;
            int rem = e - r * EW;
            float v = 0.f;
            if (i0 + r < NROWS) {
                int aa = seqs[r + (rem >> 4)];
                v = embs[aa * 16 + (rem & 15)];
            }
            xs[r * XST + GEO + rem] = v;
        }
        __syncthreads();

        // ============ layer 1: h1 = relu(x @ W1 + b1) ============
        u64 acc[4][4];   // [row][pair]: 0,1 -> cols c0+0/1, c0+2/3 ; 2,3 -> c1+...
        #pragma unroll
        for (int i = 0; i < 4; ++i)
            #pragma unroll
            for (int c = 0; c < 4; ++c) acc[i][c] = 0ULL;

        #pragma unroll 2
        for (int k = 0; k < XST; k += 4) {
            float4 xv4[4];
            #pragma unroll
            for (int i = 0; i < 4; ++i)
                xv4[i] = *(const float4*)(xs + (r0 + i) * XST + k);
            const float* xvf = (const float*)xv4;
            #pragma unroll
            for (int kk = 0; kk < 4; ++kk) {
                ulonglong2 wA = *(const ulonglong2*)(W1s + (k + kk) * 128 + c0);
                ulonglong2 wB = *(const ulonglong2*)(W1s + (k + kk) * 128 + c1);
                #pragma unroll
                for (int i = 0; i < 4; ++i) {
                    u64 xr = rep2(xvf[i * 4 + kk]);
                    acc[i][0] = ffma2(xr, wA.x, acc[i][0]);
                    acc[i][1] = ffma2(xr, wA.y, acc[i][1]);
                    acc[i][2] = ffma2(xr, wB.x, acc[i][2]);
                    acc[i][3] = ffma2(xr, wB.y, acc[i][3]);
                }
            }
        }
        {
            // bias + relu, write h1
            float4 bA = *(const float4*)(b1s + c0);
            float4 bB = *(const float4*)(b1s + c1);
            const float* bAf = (const float*)&bA;
            const float* bBf = (const float*)&bB;
            #pragma unroll
            for (int i = 0; i < 4; ++i) {
                float hA[4], hB[4];
                #pragma unroll
                for (int c = 0; c < 2; ++c) {
                    float2 vA = unpack2(acc[i][c]);
                    hA[2*c]   = fmaxf(vA.x + bAf[2*c],   0.f);
                    hA[2*c+1] = fmaxf(vA.y + bAf[2*c+1], 0.f);
                    float2 vB = unpack2(acc[i][2 + c]);
                    hB[2*c]   = fmaxf(vB.x + bBf[2*c],   0.f);
                    hB[2*c+1] = fmaxf(vB.y + bBf[2*c+1], 0.f);
                }
                *(float4*)(h1s + (r0 + i) * 128 + c0) = make_float4(hA[0], hA[1], hA[2], hA[3]);
                *(float4*)(h1s + (r0 + i) * 128 + c1) = make_float4(hB[0], hB[1], hB[2], hB[3]);
            }
        }
        __syncthreads();

        // ============ layer 2: relu(h1 @ W2 + b2) fused with layer-3 dot ============
        #pragma unroll
        for (int i = 0; i < 4; ++i)
            #pragma unroll
            for (int c = 0; c < 4; ++c) acc[i][c] = 0ULL;

        #pragma unroll 2
        for (int k = 0; k < 128; k += 4) {
            float4 hv4[4];
            #pragma unroll
            for (int i = 0; i < 4; ++i)
                hv4[i] = *(const float4*)(h1s + (r0 + i) * 128 + k);
            const float* hvf = (const float*)hv4;
            #pragma unroll
            for (int kk = 0; kk < 4; ++kk) {
                ulonglong2 wA = *(const ulonglong2*)(W2s + (k + kk) * 128 + c0);
                ulonglong2 wB = *(const ulonglong2*)(W2s + (k + kk) * 128 + c1);
                #pragma unroll
                for (int i = 0; i < 4; ++i) {
                    u64 hr = rep2(hvf[i * 4 + kk]);
                    acc[i][0] = ffma2(hr, wA.x, acc[i][0]);
                    acc[i][1] = ffma2(hr, wA.y, acc[i][1]);
                    acc[i][2] = ffma2(hr, wB.x, acc[i][2]);
                    acc[i][3] = ffma2(hr, wB.y, acc[i][3]);
                }
            }
        }

        // ---- epilogue: relu + dot with W3, 16-lane reduce per row ----
        {
            float4 bA = *(const float4*)(b2s + c0);
            float4 bB = *(const float4*)(b2s + c1);
            float4 wA3 = *(const float4*)(W3s + c0);
            float4 wB3 = *(const float4*)(W3s + c1);
            const float* bAf = (const float*)&bA;
            const float* bBf = (const float*)&bB;
            const float* wAf = (const float*)&wA3;
            const float* wBf = (const float*)&wB3;
            float p[4];
            #pragma unroll
            for (int i = 0; i < 4; ++i) {
                float s = 0.f;
                #pragma unroll
                for (int c = 0; c < 2; ++c) {
                    float2 vA = unpack2(acc[i][c]);
                    s += fmaxf(vA.x + bAf[2*c],   0.f) * wAf[2*c];
                    s += fmaxf(vA.y + bAf[2*c+1], 0.f) * wAf[2*c+1];
                    float2 vB = unpack2(acc[i][2 + c]);
                    s += fmaxf(vB.x + bBf[2*c],   0.f) * wBf[2*c];
                    s += fmaxf(vB.y + bBf[2*c+1], 0.f) * wBf[2*c+1];
                }
                p[i] = s;
            }
            #pragma unroll
            for (int off = 8; off; off >>= 1) {
                #pragma unroll
                for (int i = 0; i < 4; ++i)
                    p[i] += __shfl_down_sync(0xffffffffu, p[i], off, 16);
            }
            if ((lane & 15) == 0) {
                float s = 0.f;
                #pragma unroll
                for (int i = 0; i < 4; ++i)
                    if (i0 + r0 + i < NROWS) s += p[i] + b3r;
                atomicAdd(bsum, s);
            }
        }
    }

    __syncthreads();
    if (tid == 0) atomicAdd(&out[batch], *bsum);
}

extern "C" void kernel_launch(void* const* d_in, const int* in_sizes, int n_in,
                              void* d_out, int out_size) {
    const float* R   = (const float*)d_in[0];
    const int*   seq = (const int*)d_in[1];
    const float* emb = (const float*)d_in[2];
    const float* fl[6]; const float* ft[6]; const float* fp[6];
    for (int i = 0; i < 6; ++i) {
        fl[i] = (const float*)d_in[3 + i];
        ft[i] = (const float*)d_in[9 + i];
        fp[i] = (const float*)d_in[15 + i];
    }
    float* out = (float*)d_out;

    cudaFuncSetAttribute(mlp_energy_kernel<2>,
        cudaFuncAttributeMaxDynamicSharedMemorySize, Cfg<2>::SMEM_BYTES);
    cudaFuncSetAttribute(mlp_energy_kernel<3>,
        cudaFuncAttributeMaxDynamicSharedMemorySize, Cfg<3>::SMEM_BYTES);
    cudaFuncSetAttribute(mlp_energy_kernel<4>,
        cudaFuncAttributeMaxDynamicSharedMemorySize, Cfg<4>::SMEM_BYTES);

    zero_kernel<<<1, 256>>>(out, out_size);

    dim3 grid(BDIM * GPB);
    mlp_energy_kernel<2><<<grid, THREADS, Cfg<2>::SMEM_BYTES>>>(
        R, seq, emb, fl[0], fl[1], fl[2], fl[3], fl[4], fl[5], out);
    mlp_energy_kernel<3><<<grid, THREADS, Cfg<3>::SMEM_BYTES>>>(
        R, seq, emb, ft[0], ft[1], ft[2], ft[3], ft[4], ft[5], out);
    mlp_energy_kernel<4><<<grid, THREADS, Cfg<4>::SMEM_BYTES>>>(
        R, seq, emb, fp[0], fp[1], fp[2], fp[3], fp[4], fp[5], out);
}

// round 6
// speedup vs baseline: 2.4182x; 1.5818x over previous
#include <cuda_runtime.h>
#include <cuda_bf16.h>
#include <stdint.h>
#include <math.h>

#define THREADS  128
#define TILE     128
#define TPG      8
#define GPB      2      // CTAs per batch: 2*8*128 = 2048 rows
#define LDIM     2048
#define NBATCH   128
#define RSTRIDE_B 272   // bytes per bf16 row (136 elems: 128 + 8 pad) -> conflict-free ldmatrix
#define RSTRIDE_W 68    // u32 words per row

typedef unsigned int u32;

// ---------------- helpers ----------------
__device__ __forceinline__ u32 smem_u32(const void* p) {
    u32 a;
    asm("{ .reg .u64 t; cvta.to.shared.u64 t, %1; cvt.u32.u64 %0, t; }" : "=r"(a) : "l"(p));
    return a;
}
__device__ __forceinline__ void ldsm_x4(u32* r, u32 addr) {
    asm volatile("ldmatrix.sync.aligned.m8n8.x4.shared.b16 {%0,%1,%2,%3}, [%4];"
        : "=r"(r[0]), "=r"(r[1]), "=r"(r[2]), "=r"(r[3]) : "r"(addr));
}
__device__ __forceinline__ void ldsm_x2t(u32& r0, u32& r1, u32 addr) {
    asm volatile("ldmatrix.sync.aligned.m8n8.x2.trans.shared.b16 {%0,%1}, [%2];"
        : "=r"(r0), "=r"(r1) : "r"(addr));
}
__device__ __forceinline__ void mma16816(float* d, const u32* a, u32 b0, u32 b1) {
    asm volatile("mma.sync.aligned.m16n8k16.row.col.f32.bf16.bf16.f32 "
        "{%0,%1,%2,%3}, {%4,%5,%6,%7}, {%8,%9}, {%0,%1,%2,%3};"
        : "+f"(d[0]), "+f"(d[1]), "+f"(d[2]), "+f"(d[3])
        : "r"(a[0]), "r"(a[1]), "r"(a[2]), "r"(a[3]), "r"(b0), "r"(b1));
}
// split float pair into bf16-hi word and bf16-lo (residual) word
__device__ __forceinline__ void split_pack(float a, float b, u32& hw, u32& lw) {
    __nv_bfloat16 ah = __float2bfloat16_rn(a);
    __nv_bfloat16 bh = __float2bfloat16_rn(b);
    float al = a - __bfloat162float(ah);
    float bl = b - __bfloat162float(bh);
    __nv_bfloat16 alh = __float2bfloat16_rn(al);
    __nv_bfloat16 blh = __float2bfloat16_rn(bl);
    hw = ((u32)__bfloat16_as_ushort(bh)  << 16) | (u32)__bfloat16_as_ushort(ah);
    lw = ((u32)__bfloat16_as_ushort(blh) << 16) | (u32)__bfloat16_as_ushort(alh);
}

template<int NEMB>
struct Cfg {
    static constexpr int GEO = (NEMB == 4) ? 2 : 1;
    static constexpr int IN  = GEO + NEMB * 16;
    static constexpr int K1  = ((IN + 15) / 16) * 16;   // 48 / 64 / 80
    static constexpr int KSTEPS1 = K1 / 16;
    static constexpr int NROWS = LDIM - NEMB + 1;
    // smem byte offsets
    static constexpr int W1H = 0;
    static constexpr int W1L = W1H + K1 * RSTRIDE_B;
    static constexpr int W2H = W1L + K1 * RSTRIDE_B;
    static constexpr int W2L = W2H + 128 * RSTRIDE_B;
    static constexpr int XH  = W2L + 128 * RSTRIDE_B;   // x tile hi, later h1 hi
    static constexpr int XL  = XH  + 128 * RSTRIDE_B;   // x tile lo, later h1 lo
    static constexpr int BIAS = XL + 128 * RSTRIDE_B;   // b1,b2,W3: 3*128 floats
    static constexpr int EMB  = BIAS + 3 * 512;         // 320 floats
    static constexpr int SMEM_BYTES = EMB + 1280;
};

__global__ void zero_kernel(float* out, int n) {
    int i = blockIdx.x * blockDim.x + threadIdx.x;
    if (i < n) out[i] = 0.f;
}

// one GEMM stage: acc += Ah*Bh + Ah*Bl + Al*Bh  (M=32/warp, N=128, K=16*KSTEPS)
template<int KSTEPS>
__device__ __forceinline__ void gemm_stage(float acc[16][2][4],
                                           u32 ah_base, u32 al_base,
                                           u32 bh_base, u32 bl_base,
                                           u32 aoff0, u32 aoff1, u32 boff)
{
    #pragma unroll 1
    for (int k = 0; k < KSTEPS; ++k) {
        u32 ah0[4], ah1[4], al0[4], al1[4];
        ldsm_x4(ah0, ah_base + aoff0 + k * 32);
        ldsm_x4(ah1, ah_base + aoff1 + k * 32);
        ldsm_x4(al0, al_base + aoff0 + k * 32);
        ldsm_x4(al1, al_base + aoff1 + k * 32);
        u32 bk = boff + (u32)k * 16 * RSTRIDE_B;
        #pragma unroll
        for (int nf = 0; nf < 16; ++nf) {
            u32 bh0, bh1, bl0, bl1;
            ldsm_x2t(bh0, bh1, bh_base + bk + nf * 16);
            ldsm_x2t(bl0, bl1, bl_base + bk + nf * 16);
            mma16816(acc[nf][0], ah0, bh0, bh1);
            mma16816(acc[nf][1], ah1, bh0, bh1);
            mma16816(acc[nf][0], ah0, bl0, bl1);
            mma16816(acc[nf][1], ah1, bl0, bl1);
            mma16816(acc[nf][0], al0, bh0, bh1);
            mma16816(acc[nf][1], al1, bh0, bh1);
        }
    }
}

template<int NEMB>
__global__ __launch_bounds__(THREADS, 1)
void mlp_energy_mma(const float* __restrict__ R,
                    const int*   __restrict__ seq,
                    const float* __restrict__ emb,
                    const float* __restrict__ gW1, const float* __restrict__ gb1,
                    const float* __restrict__ gW2, const float* __restrict__ gb2,
                    const float* __restrict__ gW3, const float* __restrict__ gb3,
                    float* __restrict__ out)
{
    constexpr int GEO   = Cfg<NEMB>::GEO;
    constexpr int IN    = Cfg<NEMB>::IN;
    constexpr int K1    = Cfg<NEMB>::K1;
    constexpr int NROWS = Cfg<NEMB>::NROWS;

    extern __shared__ char smem[];
    float* b1s  = (float*)(smem + Cfg<NEMB>::BIAS);
    float* b2s  = b1s + 128;
    float* W3s  = b2s + 128;
    float* embs = (float*)(smem + Cfg<NEMB>::EMB);

    const int tid  = threadIdx.x;
    const int wid  = tid >> 5;
    const int lane = tid & 31;
    const int batch = blockIdx.x / GPB;
    const int group = blockIdx.x % GPB;

    // ---- stage biases / emb ----
    b1s[tid] = gb1[tid]; b2s[tid] = gb2[tid]; W3s[tid] = gW3[tid];
    for (int i = tid; i < 320; i += THREADS) embs[i] = emb[i];
    // ---- stage W1 (zero-padded to K1 rows), split hi/lo, K-major [K][128] ----
    {
        u32* wh = (u32*)(smem + Cfg<NEMB>::W1H);
        u32* wl = (u32*)(smem + Cfg<NEMB>::W1L);
        for (int idx = tid; idx < K1 * 64; idx += THREADS) {
            int k = idx >> 6, np = idx & 63;
            int n = 2 * np;
            float w0 = (k < IN) ? gW1[(size_t)k * 128 + n]     : 0.f;
            float w1 = (k < IN) ? gW1[(size_t)k * 128 + n + 1] : 0.f;
            u32 hw, lw; split_pack(w0, w1, hw, lw);
            wh[k * RSTRIDE_W + np] = hw;
            wl[k * RSTRIDE_W + np] = lw;
        }
    }
    // ---- stage W2 ----
    {
        u32* wh = (u32*)(smem + Cfg<NEMB>::W2H);
        u32* wl = (u32*)(smem + Cfg<NEMB>::W2L);
        for (int idx = tid; idx < 128 * 64; idx += THREADS) {
            int k = idx >> 6, np = idx & 63;
            int n = 2 * np;
            float w0 = gW2[(size_t)k * 128 + n];
            float w1 = gW2[(size_t)k * 128 + n + 1];
            u32 hw, lw; split_pack(w0, w1, hw, lw);
            wh[k * RSTRIDE_W + np] = hw;
            wl[k * RSTRIDE_W + np] = lw;
        }
    }
    __syncthreads();

    const float b3r = gb3[0];
    const float* Rb   = R   + (size_t)batch * LDIM * 3;
    const int*   seqb = seq + (size_t)batch * LDIM;

    // ldmatrix base/thread offsets
    const u32 xh_b = smem_u32(smem + Cfg<NEMB>::XH);
    const u32 xl_b = smem_u32(smem + Cfg<NEMB>::XL);
    const u32 w1h_b = smem_u32(smem + Cfg<NEMB>::W1H);
    const u32 w1l_b = smem_u32(smem + Cfg<NEMB>::W1L);
    const u32 w2h_b = smem_u32(smem + Cfg<NEMB>::W2H);
    const u32 w2l_b = smem_u32(smem + Cfg<NEMB>::W2L);
    const int m0 = wid * 32;
    const u32 aoff0 = (u32)(m0 + (lane & 15)) * RSTRIDE_B + (u32)(lane >> 4) * 16;
    const u32 aoff1 = aoff0 + 16 * RSTRIDE_B;
    const u32 boff  = (u32)(lane & 15) * RSTRIDE_B;

    u32* hh = (u32*)(smem + Cfg<NEMB>::XH);
    u32* hl = (u32*)(smem + Cfg<NEMB>::XL);
    const int tq = lane >> 2;       // 0..7
    const int tc = 2 * (lane & 3);  // 0,2,4,6

    float acc_e = 0.f;

    for (int tt = 0; tt < TPG; ++tt) {
        const int i0 = (group * TPG + tt) * TILE;

        // ---- build x row (thread = row), write bf16 hi/lo directly ----
        {
            const int row = tid;
            const int i = i0 + row;
            const bool valid = (i < NROWS);
            float g0 = 0.f, g1 = 0.f;
            int sv[NEMB];
            #pragma unroll
            for (int v = 0; v < NEMB; ++v) sv[v] = valid ? seqb[i + v] : 0;
            if (valid) {
                float p0x = Rb[i*3+0],     p0y = Rb[i*3+1],     p0z = Rb[i*3+2];
                float p1x = Rb[(i+1)*3+0], p1y = Rb[(i+1)*3+1], p1z = Rb[(i+1)*3+2];
                float d0x = p1x - p0x, d0y = p1y - p0y, d0z = p1z - p0z;
                if (NEMB == 2) {
                    g0 = sqrtf(d0x*d0x + d0y*d0y + d0z*d0z);
                } else if (NEMB == 3) {
                    float p2x = Rb[(i+2)*3+0], p2y = Rb[(i+2)*3+1], p2z = Rb[(i+2)*3+2];
                    float d1x = p2x - p1x, d1y = p2y - p1y, d1z = p2z - p1z;
                    float dot01 = d0x*d1x + d0y*d1y + d0z*d1z;
                    float n0 = d0x*d0x + d0y*d0y + d0z*d0z;
                    float n1 = d1x*d1x + d1y*d1y + d1z*d1z;
                    float c  = -dot01 / (sqrtf(n0) * sqrtf(n1));
                    g0 = fminf(1.f, fmaxf(-1.f, c));
                } else {
                    float p2x = Rb[(i+2)*3+0], p2y = Rb[(i+2)*3+1], p2z = Rb[(i+2)*3+2];
                    float p3x = Rb[(i+3)*3+0], p3y = Rb[(i+3)*3+1], p3z = Rb[(i+3)*3+2];
                    float d1x = p2x - p1x, d1y = p2y - p1y, d1z = p2z - p1z;
                    float d2x = p3x - p2x, d2y = p3y - p2y, d2z = p3z - p2z;
                    float n1x = d0y*d1z - d0z*d1y;
                    float n1y = d0z*d1x - d0x*d1z;
                    float n1z = d0x*d1y - d0y*d1x;
                    float n2x = d1y*d2z - d1z*d2y;
                    float n2y = d1z*d2x - d1x*d2z;
                    float n2z = d1x*d2y - d1y*d2x;
                    float inv = rsqrtf(d1x*d1x + d1y*d1y + d1z*d1z);
                    float ux = d1x*inv, uy = d1y*inv, uz = d1z*inv;
                    float m1x = n1y*uz - n1z*uy;
                    float m1y = n1z*ux - n1x*uz;
                    float m1z = n1x*uy - n1y*ux;
                    float yv = m1x*n2x + m1y*n2y + m1z*n2z;
                    float xv = n1x*n2x + n1y*n2y + n1z*n2z;
                    float rinv = rsqrtf(xv*xv + yv*yv);
                    g0 = yv * rinv;   // sin(phi)
                    g1 = xv * rinv;   // cos(phi)
                }
            }
            u32* xh = hh + row * RSTRIDE_W;
            u32* xl = hl + row * RSTRIDE_W;
            #pragma unroll
            for (int p = 0; p < K1 / 2; ++p) {
                float v0, v1;
                {   const int c = 2 * p;
                    if (c < GEO)            v0 = (c == 0) ? g0 : g1;
                    else if (c < IN)        { int j = c - GEO; v0 = valid ? embs[sv[j >> 4] * 16 + (j & 15)] : 0.f; }
                    else                    v0 = 0.f;
                }
                {   const int c = 2 * p + 1;
                    if (c < GEO)            v1 = g1;
                    else if (c < IN)        { int j = c - GEO; v1 = valid ? embs[sv[j >> 4] * 16 + (j & 15)] : 0.f; }
                    else                    v1 = 0.f;
                }
                if (!valid) { v0 = 0.f; v1 = 0.f; }
                u32 hw, lw; split_pack(v0, v1, hw, lw);
                xh[p] = hw; xl[p] = lw;
            }
        }
        __syncwarp();

        // ---- layer 1 GEMM ----
        float acc[16][2][4];
        #pragma unroll
        for (int nf = 0; nf < 16; ++nf)
            #pragma unroll
            for (int mf = 0; mf < 2; ++mf)
                #pragma unroll
                for (int q = 0; q < 4; ++q) acc[nf][mf][q] = 0.f;

        gemm_stage<Cfg<NEMB>::KSTEPS1>(acc, xh_b, xl_b, w1h_b, w1l_b, aoff0, aoff1, boff);

        // ---- epilogue 1: relu(+b1), split, write h1 (aliases x buffers) ----
        #pragma unroll
        for (int nf = 0; nf < 16; ++nf) {
            const int c0 = nf * 8 + tc;
            float2 bv = *(const float2*)(b1s + c0);
            #pragma unroll
            for (int mf = 0; mf < 2; ++mf) {
                int r = m0 + mf * 16 + tq;
                float v0 = fmaxf(acc[nf][mf][0] + bv.x, 0.f);
                float v1 = fmaxf(acc[nf][mf][1] + bv.y, 0.f);
                u32 hw, lw; split_pack(v0, v1, hw, lw);
                hh[r * RSTRIDE_W + c0 / 2] = hw;
                hl[r * RSTRIDE_W + c0 / 2] = lw;
                v0 = fmaxf(acc[nf][mf][2] + bv.x, 0.f);
                v1 = fmaxf(acc[nf][mf][3] + bv.y, 0.f);
                split_pack(v0, v1, hw, lw);
                hh[(r + 8) * RSTRIDE_W + c0 / 2] = hw;
                hl[(r + 8) * RSTRIDE_W + c0 / 2] = lw;
            }
        }
        __syncwarp();

        // ---- layer 2 GEMM ----
        #pragma unroll
        for (int nf = 0; nf < 16; ++nf)
            #pragma unroll
            for (int mf = 0; mf < 2; ++mf)
                #pragma unroll
                for (int q = 0; q < 4; ++q) acc[nf][mf][q] = 0.f;

        gemm_stage<8>(acc, xh_b, xl_b, w2h_b, w2l_b, aoff0, aoff1, boff);

        // ---- epilogue 2: relu(+b2) dot W3, quad-reduce, accumulate ----
        {
            float s[4] = {0.f, 0.f, 0.f, 0.f};  // rows: m0+tq, +8, m0+16+tq, +24
            #pragma unroll
            for (int nf = 0; nf < 16; ++nf) {
                const int c0 = nf * 8 + tc;
                float2 bv = *(const float2*)(b2s + c0);
                float2 wv = *(const float2*)(W3s + c0);
                s[0] += fmaxf(acc[nf][0][0] + bv.x, 0.f) * wv.x
                      + fmaxf(acc[nf][0][1] + bv.y, 0.f) * wv.y;
                s[1] += fmaxf(acc[nf][0][2] + bv.x, 0.f) * wv.x
                      + fmaxf(acc[nf][0][3] + bv.y, 0.f) * wv.y;
                s[2] += fmaxf(acc[nf][1][0] + bv.x, 0.f) * wv.x
                      + fmaxf(acc[nf][1][1] + bv.y, 0.f) * wv.y;
                s[3] += fmaxf(acc[nf][1][2] + bv.x, 0.f) * wv.x
                      + fmaxf(acc[nf][1][3] + bv.y, 0.f) * wv.y;
            }
            #pragma unroll
            for (int d = 1; d <= 2; d <<= 1)
                #pragma unroll
                for (int q = 0; q < 4; ++q)
                    s[q] += __shfl_xor_sync(0xffffffffu, s[q], d);
            if ((lane & 3) == 0) {
                const int rows[4] = { m0 + tq, m0 + tq + 8, m0 + 16 + tq, m0 + 24 + tq };
                #pragma unroll
                for (int q = 0; q < 4; ++q)
                    if (i0 + rows[q] < NROWS) acc_e += s[q] + b3r;
            }
        }
        __syncwarp();
    }

    // ---- warp reduce + atomic ----
    #pragma unroll
    for (int off = 16; off; off >>= 1)
        acc_e += __shfl_down_sync(0xffffffffu, acc_e, off);
    if (lane == 0) atomicAdd(&out[batch], acc_e);
}

extern "C" void kernel_launch(void* const* d_in, const int* in_sizes, int n_in,
                              void* d_out, int out_size) {
    const float* R   = (const float*)d_in[0];
    const int*   seq = (const int*)d_in[1];
    const float* emb = (const float*)d_in[2];
    const float* fl[6]; const float* ft[6]; const float* fp[6];
    for (int i = 0; i < 6; ++i) {
        fl[i] = (const float*)d_in[3 + i];
        ft[i] = (const float*)d_in[9 + i];
        fp[i] = (const float*)d_in[15 + i];
    }
    float* out = (float*)d_out;

    cudaFuncSetAttribute(mlp_energy_mma<2>,
        cudaFuncAttributeMaxDynamicSharedMemorySize, Cfg<2>::SMEM_BYTES);
    cudaFuncSetAttribute(mlp_energy_mma<3>,
        cudaFuncAttributeMaxDynamicSharedMemorySize, Cfg<3>::SMEM_BYTES);
    cudaFuncSetAttribute(mlp_energy_mma<4>,
        cudaFuncAttributeMaxDynamicSharedMemorySize, Cfg<4>::SMEM_BYTES);

    zero_kernel<<<1, 256>>>(out, out_size);

    dim3 grid(NBATCH * GPB);
    mlp_energy_mma<2><<<grid, THREADS, Cfg<2>::SMEM_BYTES>>>(
        R, seq, emb, fl[0], fl[1], fl[2], fl[3], fl[4], fl[5], out);
    mlp_energy_mma<3><<<grid, THREADS, Cfg<3>::SMEM_BYTES>>>(
        R, seq, emb, ft[0], ft[1], ft[2], ft[3], ft[4], ft[5], out);
    mlp_energy_mma<4><<<grid, THREADS, Cfg<4>::SMEM_BYTES>>>(
        R, seq, emb, fp[0], fp[1], fp[2], fp[3], fp[4], fp[5], out);
}

// round 7
// speedup vs baseline: 2.4693x; 1.0211x over previous
#include <cuda_runtime.h>
#include <cuda_bf16.h>
#include <stdint.h>
#include <math.h>

#define THREADS  256
#define TILE     128
#define TPG      2
#define GPB      8      // CTAs per batch: 8*2*128 = 2048 rows
#define LDIM     2048
#define NBATCH   128
#define RSTRIDE_B 272   // bytes per bf16 row (136 elems) -> conflict-free ldmatrix
#define RSTRIDE_W 68    // u32 words per row

typedef unsigned int u32;

// ---------------- helpers ----------------
__device__ __forceinline__ u32 smem_u32(const void* p) {
    u32 a;
    asm("{ .reg .u64 t; cvta.to.shared.u64 t, %1; cvt.u32.u64 %0, t; }" : "=r"(a) : "l"(p));
    return a;
}
__device__ __forceinline__ void ldsm_x4(u32* r, u32 addr) {
    asm volatile("ldmatrix.sync.aligned.m8n8.x4.shared.b16 {%0,%1,%2,%3}, [%4];"
        : "=r"(r[0]), "=r"(r[1]), "=r"(r[2]), "=r"(r[3]) : "r"(addr));
}
__device__ __forceinline__ void ldsm_x2t(u32& r0, u32& r1, u32 addr) {
    asm volatile("ldmatrix.sync.aligned.m8n8.x2.trans.shared.b16 {%0,%1}, [%2];"
        : "=r"(r0), "=r"(r1) : "r"(addr));
}
__device__ __forceinline__ void mma16816(float* d, const u32* a, u32 b0, u32 b1) {
    asm volatile("mma.sync.aligned.m16n8k16.row.col.f32.bf16.bf16.f32 "
        "{%0,%1,%2,%3}, {%4,%5,%6,%7}, {%8,%9}, {%0,%1,%2,%3};"
        : "+f"(d[0]), "+f"(d[1]), "+f"(d[2]), "+f"(d[3])
        : "r"(a[0]), "r"(a[1]), "r"(a[2]), "r"(a[3]), "r"(b0), "r"(b1));
}
__device__ __forceinline__ void split_pack(float a, float b, u32& hw, u32& lw) {
    __nv_bfloat16 ah = __float2bfloat16_rn(a);
    __nv_bfloat16 bh = __float2bfloat16_rn(b);
    float al = a - __bfloat162float(ah);
    float bl = b - __bfloat162float(bh);
    __nv_bfloat16 alh = __float2bfloat16_rn(al);
    __nv_bfloat16 blh = __float2bfloat16_rn(bl);
    hw = ((u32)__bfloat16_as_ushort(bh)  << 16) | (u32)__bfloat16_as_ushort(ah);
    lw = ((u32)__bfloat16_as_ushort(blh) << 16) | (u32)__bfloat16_as_ushort(alh);
}

template<int NEMB>
struct Cfg {
    static constexpr int GEO = (NEMB == 4) ? 2 : 1;
    static constexpr int IN  = GEO + NEMB * 16;
    static constexpr int K1  = ((IN + 15) / 16) * 16;   // 48 / 64 / 80
    static constexpr int KSTEPS1 = K1 / 16;
    static constexpr int NROWS = LDIM - NEMB + 1;
    static constexpr int W1H = 0;
    static constexpr int W1L = W1H + K1 * RSTRIDE_B;
    static constexpr int W2H = W1L + K1 * RSTRIDE_B;
    static constexpr int W2L = W2H + 128 * RSTRIDE_B;
    static constexpr int XH  = W2L + 128 * RSTRIDE_B;   // x tile hi, later h1 hi
    static constexpr int XL  = XH  + 128 * RSTRIDE_B;   // x tile lo, later h1 lo
    static constexpr int BIAS = XL + 128 * RSTRIDE_B;   // b1,b2,W3: 3*128 floats
    static constexpr int EMB  = BIAS + 3 * 512;         // 320 floats
    static constexpr int SMEM_BYTES = EMB + 1280;
};

__global__ void zero_kernel(float* out, int n) {
    int i = blockIdx.x * blockDim.x + threadIdx.x;
    if (i < n) out[i] = 0.f;
}

// acc += Ah*Bh + Ah*Bl + Al*Bh  (M=32 rows, N=64 col-half, K=16*KSTEPS)
template<int KSTEPS>
__device__ __forceinline__ void gemm_stage(float acc[8][2][4],
                                           u32 ah_base, u32 al_base,
                                           u32 bh_base, u32 bl_base,
                                           u32 aoff0, u32 aoff1, u32 boff)
{
    #pragma unroll 1
    for (int k = 0; k < KSTEPS; ++k) {
        u32 ah0[4], ah1[4], al0[4], al1[4];
        ldsm_x4(ah0, ah_base + aoff0 + k * 32);
        ldsm_x4(ah1, ah_base + aoff1 + k * 32);
        ldsm_x4(al0, al_base + aoff0 + k * 32);
        ldsm_x4(al1, al_base + aoff1 + k * 32);
        u32 bk = boff + (u32)k * 16 * RSTRIDE_B;
        #pragma unroll
        for (int nf = 0; nf < 8; ++nf) {
            u32 bh0, bh1, bl0, bl1;
            ldsm_x2t(bh0, bh1, bh_base + bk + nf * 16);
            ldsm_x2t(bl0, bl1, bl_base + bk + nf * 16);
            mma16816(acc[nf][0], ah0, bh0, bh1);
            mma16816(acc[nf][1], ah1, bh0, bh1);
            mma16816(acc[nf][0], ah0, bl0, bl1);
            mma16816(acc[nf][1], ah1, bl0, bl1);
            mma16816(acc[nf][0], al0, bh0, bh1);
            mma16816(acc[nf][1], al1, bh0, bh1);
        }
    }
}

template<int NEMB>
__global__ __launch_bounds__(THREADS, 1)
void mlp_energy_mma(const float* __restrict__ R,
                    const int*   __restrict__ seq,
                    const float* __restrict__ emb,
                    const float* __restrict__ gW1, const float* __restrict__ gb1,
                    const float* __restrict__ gW2, const float* __restrict__ gb2,
                    const float* __restrict__ gW3, const float* __restrict__ gb3,
                    float* __restrict__ out)
{
    constexpr int GEO   = Cfg<NEMB>::GEO;
    constexpr int IN    = Cfg<NEMB>::IN;
    constexpr int K1    = Cfg<NEMB>::K1;
    constexpr int NROWS = Cfg<NEMB>::NROWS;

    extern __shared__ char smem[];
    float* b1s  = (float*)(smem + Cfg<NEMB>::BIAS);
    float* b2s  = b1s + 128;
    float* W3s  = b2s + 128;
    float* embs = (float*)(smem + Cfg<NEMB>::EMB);

    const int tid  = threadIdx.x;
    const int wid  = tid >> 5;
    const int lane = tid & 31;
    const int batch = blockIdx.x / GPB;
    const int group = blockIdx.x % GPB;

    // ---- stage biases / emb ----
    if (tid < 128) { b1s[tid] = gb1[tid]; b2s[tid] = gb2[tid]; W3s[tid] = gW3[tid]; }
    for (int i = tid; i < 320; i += THREADS) embs[i] = emb[i];
    // ---- stage W1 (zero-padded to K1 rows), split hi/lo, K-major [K][128] ----
    {
        u32* wh = (u32*)(smem + Cfg<NEMB>::W1H);
        u32* wl = (u32*)(smem + Cfg<NEMB>::W1L);
        for (int idx = tid; idx < K1 * 64; idx += THREADS) {
            int k = idx >> 6, np = idx & 63;
            int n = 2 * np;
            float w0 = (k < IN) ? gW1[(size_t)k * 128 + n]     : 0.f;
            float w1 = (k < IN) ? gW1[(size_t)k * 128 + n + 1] : 0.f;
            u32 hw, lw; split_pack(w0, w1, hw, lw);
            wh[k * RSTRIDE_W + np] = hw;
            wl[k * RSTRIDE_W + np] = lw;
        }
    }
    // ---- stage W2 ----
    {
        u32* wh = (u32*)(smem + Cfg<NEMB>::W2H);
        u32* wl = (u32*)(smem + Cfg<NEMB>::W2L);
        for (int idx = tid; idx < 128 * 64; idx += THREADS) {
            int k = idx >> 6, np = idx & 63;
            int n = 2 * np;
            float w0 = gW2[(size_t)k * 128 + n];
            float w1 = gW2[(size_t)k * 128 + n + 1];
            u32 hw, lw; split_pack(w0, w1, hw, lw);
            wh[k * RSTRIDE_W + np] = hw;
            wl[k * RSTRIDE_W + np] = lw;
        }
    }
    __syncthreads();

    const float b3r = gb3[0];
    const float* Rb   = R   + (size_t)batch * LDIM * 3;
    const int*   seqb = seq + (size_t)batch * LDIM;

    const u32 xh_b  = smem_u32(smem + Cfg<NEMB>::XH);
    const u32 xl_b  = smem_u32(smem + Cfg<NEMB>::XL);
    const u32 w1h_b = smem_u32(smem + Cfg<NEMB>::W1H);
    const u32 w1l_b = smem_u32(smem + Cfg<NEMB>::W1L);
    const u32 w2h_b = smem_u32(smem + Cfg<NEMB>::W2H);
    const u32 w2l_b = smem_u32(smem + Cfg<NEMB>::W2L);

    const int rg = wid >> 1;           // row group 0..3  -> rows 32*rg..
    const int ch = wid & 1;            // N col-half 0/1  -> cols 64*ch..
    const int m0 = rg * 32;
    const u32 aoff0 = (u32)(m0 + (lane & 15)) * RSTRIDE_B + (u32)(lane >> 4) * 16;
    const u32 aoff1 = aoff0 + 16 * RSTRIDE_B;
    const u32 boff  = (u32)(lane & 15) * RSTRIDE_B + (u32)ch * 128;  // 64 cols = 128 B

    u32* hh = (u32*)(smem + Cfg<NEMB>::XH);
    u32* hl = (u32*)(smem + Cfg<NEMB>::XL);
    const int tq = lane >> 2;       // 0..7
    const int tc = 2 * (lane & 3);  // 0,2,4,6

    float acc_e = 0.f;

    for (int tt = 0; tt < TPG; ++tt) {
        const int i0 = (group * TPG + tt) * TILE;
        __syncthreads();   // previous tile fully consumed

        // ---- build x row (thread=row, tid<128), bf16 hi/lo ----
        if (tid < TILE) {
            const int row = tid;
            const int i = i0 + row;
            const bool valid = (i < NROWS);
            float g0 = 0.f, g1 = 0.f;
            int sv[NEMB];
            #pragma unroll
            for (int v = 0; v < NEMB; ++v) sv[v] = valid ? seqb[i + v] : 0;
            if (valid) {
                float p0x = Rb[i*3+0],     p0y = Rb[i*3+1],     p0z = Rb[i*3+2];
                float p1x = Rb[(i+1)*3+0], p1y = Rb[(i+1)*3+1], p1z = Rb[(i+1)*3+2];
                float d0x = p1x - p0x, d0y = p1y - p0y, d0z = p1z - p0z;
                if (NEMB == 2) {
                    g0 = sqrtf(d0x*d0x + d0y*d0y + d0z*d0z);
                } else if (NEMB == 3) {
                    float p2x = Rb[(i+2)*3+0], p2y = Rb[(i+2)*3+1], p2z = Rb[(i+2)*3+2];
                    float d1x = p2x - p1x, d1y = p2y - p1y, d1z = p2z - p1z;
                    float dot01 = d0x*d1x + d0y*d1y + d0z*d1z;
                    float n0 = d0x*d0x + d0y*d0y + d0z*d0z;
                    float n1 = d1x*d1x + d1y*d1y + d1z*d1z;
                    float c  = -dot01 / (sqrtf(n0) * sqrtf(n1));
                    g0 = fminf(1.f, fmaxf(-1.f, c));
                } else {
                    float p2x = Rb[(i+2)*3+0], p2y = Rb[(i+2)*3+1], p2z = Rb[(i+2)*3+2];
                    float p3x = Rb[(i+3)*3+0], p3y = Rb[(i+3)*3+1], p3z = Rb[(i+3)*3+2];
                    float d1x = p2x - p1x, d1y = p2y - p1y, d1z = p2z - p1z;
                    float d2x = p3x - p2x, d2y = p3y - p2y, d2z = p3z - p2z;
                    float n1x = d0y*d1z - d0z*d1y;
                    float n1y = d0z*d1x - d0x*d1z;
                    float n1z = d0x*d1y - d0y*d1x;
                    float n2x = d1y*d2z - d1z*d2y;
                    float n2y = d1z*d2x - d1x*d2z;
                    float n2z = d1x*d2y - d1y*d2x;
                    float inv = rsqrtf(d1x*d1x + d1y*d1y + d1z*d1z);
                    float ux = d1x*inv, uy = d1y*inv, uz = d1z*inv;
                    float m1x = n1y*uz - n1z*uy;
                    float m1y = n1z*ux - n1x*uz;
                    float m1z = n1x*uy - n1y*ux;
                    float yv = m1x*n2x + m1y*n2y + m1z*n2z;
                    float xv = n1x*n2x + n1y*n2y + n1z*n2z;
                    float rinv = rsqrtf(xv*xv + yv*yv);
                    g0 = yv * rinv;
                    g1 = xv * rinv;
                }
            }
            u32* xh = hh + row * RSTRIDE_W;
            u32* xl = hl + row * RSTRIDE_W;
            #pragma unroll
            for (int p = 0; p < K1 / 2; ++p) {
                float v0, v1;
                {   const int c = 2 * p;
                    if (c < GEO)      v0 = (c == 0) ? g0 : g1;
                    else if (c < IN)  { int j = c - GEO; v0 = valid ? embs[sv[j >> 4] * 16 + (j & 15)] : 0.f; }
                    else              v0 = 0.f;
                }
                {   const int c = 2 * p + 1;
                    if (c < GEO)      v1 = g1;
                    else if (c < IN)  { int j = c - GEO; v1 = valid ? embs[sv[j >> 4] * 16 + (j & 15)] : 0.f; }
                    else              v1 = 0.f;
                }
                if (!valid) { v0 = 0.f; v1 = 0.f; }
                u32 hw, lw; split_pack(v0, v1, hw, lw);
                xh[p] = hw; xl[p] = lw;
            }
        }
        __syncthreads();

        // ---- layer 1 GEMM (M=32, N=64 half) ----
        float acc[8][2][4];
        #pragma unroll
        for (int nf = 0; nf < 8; ++nf)
            #pragma unroll
            for (int mf = 0; mf < 2; ++mf)
                #pragma unroll
                for (int q = 0; q < 4; ++q) acc[nf][mf][q] = 0.f;

        gemm_stage<Cfg<NEMB>::KSTEPS1>(acc, xh_b, xl_b, w1h_b, w1l_b, aoff0, aoff1, boff);
        __syncthreads();   // all reads of x done before h overwrite

        // ---- epilogue 1: relu(+b1), split, write h1 (aliases x buffers) ----
        #pragma unroll
        for (int nf = 0; nf < 8; ++nf) {
            const int c0 = ch * 64 + nf * 8 + tc;
            float2 bv = *(const float2*)(b1s + c0);
            #pragma unroll
            for (int mf = 0; mf < 2; ++mf) {
                int r = m0 + mf * 16 + tq;
                float v0 = fmaxf(acc[nf][mf][0] + bv.x, 0.f);
                float v1 = fmaxf(acc[nf][mf][1] + bv.y, 0.f);
                u32 hw, lw; split_pack(v0, v1, hw, lw);
                hh[r * RSTRIDE_W + c0 / 2] = hw;
                hl[r * RSTRIDE_W + c0 / 2] = lw;
                v0 = fmaxf(acc[nf][mf][2] + bv.x, 0.f);
                v1 = fmaxf(acc[nf][mf][3] + bv.y, 0.f);
                split_pack(v0, v1, hw, lw);
                hh[(r + 8) * RSTRIDE_W + c0 / 2] = hw;
                hl[(r + 8) * RSTRIDE_W + c0 / 2] = lw;
            }
        }
        __syncthreads();

        // ---- layer 2 GEMM ----
        #pragma unroll
        for (int nf = 0; nf < 8; ++nf)
            #pragma unroll
            for (int mf = 0; mf < 2; ++mf)
                #pragma unroll
                for (int q = 0; q < 4; ++q) acc[nf][mf][q] = 0.f;

        gemm_stage<8>(acc, xh_b, xl_b, w2h_b, w2l_b, aoff0, aoff1, boff);

        // ---- epilogue 2: relu(+b2) dot W3, quad-reduce ----
        {
            float s[4] = {0.f, 0.f, 0.f, 0.f};
            #pragma unroll
            for (int nf = 0; nf < 8; ++nf) {
                const int c0 = ch * 64 + nf * 8 + tc;
                float2 bv = *(const float2*)(b2s + c0);
                float2 wv = *(const float2*)(W3s + c0);
                s[0] += fmaxf(acc[nf][0][0] + bv.x, 0.f) * wv.x
                      + fmaxf(acc[nf][0][1] + bv.y, 0.f) * wv.y;
                s[1] += fmaxf(acc[nf][0][2] + bv.x, 0.f) * wv.x
                      + fmaxf(acc[nf][0][3] + bv.y, 0.f) * wv.y;
                s[2] += fmaxf(acc[nf][1][0] + bv.x, 0.f) * wv.x
                      + fmaxf(acc[nf][1][1] + bv.y, 0.f) * wv.y;
                s[3] += fmaxf(acc[nf][1][2] + bv.x, 0.f) * wv.x
                      + fmaxf(acc[nf][1][3] + bv.y, 0.f) * wv.y;
            }
            #pragma unroll
            for (int d = 1; d <= 2; d <<= 1)
                #pragma unroll
                for (int q = 0; q < 4; ++q)
                    s[q] += __shfl_xor_sync(0xffffffffu, s[q], d);
            if ((lane & 3) == 0) {
                const int rows[4] = { m0 + tq, m0 + tq + 8, m0 + 16 + tq, m0 + 24 + tq };
                #pragma unroll
                for (int q = 0; q < 4; ++q)
                    if (i0 + rows[q] < NROWS)
                        acc_e += s[q] + (ch == 0 ? b3r : 0.f);   // b3 added once per row
            }
        }
    }

    // ---- warp reduce + atomic ----
    #pragma unroll
    for (int off = 16; off; off >>= 1)
        acc_e += __shfl_down_sync(0xffffffffu, acc_e, off);
    if (lane == 0) atomicAdd(&out[batch], acc_e);
}

extern "C" void kernel_launch(void* const* d_in, const int* in_sizes, int n_in,
                              void* d_out, int out_size) {
    const float* R   = (const float*)d_in[0];
    const int*   seq = (const int*)d_in[1];
    const float* emb = (const float*)d_in[2];
    const float* fl[6]; const float* ft[6]; const float* fp[6];
    for (int i = 0; i < 6; ++i) {
        fl[i] = (const float*)d_in[3 + i];
        ft[i] = (const float*)d_in[9 + i];
        fp[i] = (const float*)d_in[15 + i];
    }
    float* out = (float*)d_out;

    cudaFuncSetAttribute(mlp_energy_mma<2>,
        cudaFuncAttributeMaxDynamicSharedMemorySize, Cfg<2>::SMEM_BYTES);
    cudaFuncSetAttribute(mlp_energy_mma<3>,
        cudaFuncAttributeMaxDynamicSharedMemorySize, Cfg<3>::SMEM_BYTES);
    cudaFuncSetAttribute(mlp_energy_mma<4>,
        cudaFuncAttributeMaxDynamicSharedMemorySize, Cfg<4>::SMEM_BYTES);

    zero_kernel<<<1, 256>>>(out, out_size);

    dim3 grid(NBATCH * GPB);
    mlp_energy_mma<2><<<grid, THREADS, Cfg<2>::SMEM_BYTES>>>(
        R, seq, emb, fl[0], fl[1], fl[2], fl[3], fl[4], fl[5], out);
    mlp_energy_mma<3><<<grid, THREADS, Cfg<3>::SMEM_BYTES>>>(
        R, seq, emb, ft[0], ft[1], ft[2], ft[3], ft[4], ft[5], out);
    mlp_energy_mma<4><<<grid, THREADS, Cfg<4>::SMEM_BYTES>>>(
        R, seq, emb, fp[0], fp[1], fp[2], fp[3], fp[4], fp[5], out);
}